// round 4
// baseline (speedup 1.0000x reference)
#include <cuda_runtime.h>
#include <cstdint>

// libdevice precise expf (what XLA lowers jnp.exp(f32) to), immune to fast-math.
extern "C" __device__ float __nv_expf(float);

typedef unsigned long long ull;

// ---------------- problem constants ----------------
#define N_IMG 8
#define N_ANCH 250000
#define N_ANCH4 62500
#define K_PRE 2000
#define K_POST 1000
#define CAND_CAP 4096
#define NMS_THRESH 0.7f
#define XFORM_CLIP 4.135166556742356f
#define XMAX 1332.0f
#define YMAX 799.0f
#define NEG_BIG -1e9f
#define NBINS 4096

// ---------------- device scratch ----------------
__device__ unsigned int g_hist[N_IMG * NBINS];   // zero-init at load; self-zeroed by scan
__device__ unsigned int g_state[N_IMG * 4];      // [0]=threshold key, [2]=cand_cnt (reset by sortdec)
__device__ ull    g_cand[N_IMG * CAND_CAP];
__device__ float4 g_props4[N_IMG * K_PRE];
__device__ float  g_area[N_IMG * K_PRE];
__device__ float  g_scores[N_IMG * K_PRE];
__device__ unsigned char g_valid[N_IMG * K_PRE];
__device__ ull    g_mask[N_IMG * 2048 * 32];

__device__ __forceinline__ unsigned int okey_of(float f) {
    unsigned int b = __float_as_uint(f);
    return b ^ ((b & 0x80000000u) ? 0xFFFFFFFFu : 0x80000000u);
}

// ---------------- histogram (12-bit bins), MLP=8 tiled loads ----------------
__global__ void hist_kernel(const float4* __restrict__ obj4) {
    int img = blockIdx.y, t = threadIdx.x;
    __shared__ unsigned int sh[2][NBINS];
    for (int i = t; i < 2 * NBINS; i += 256) ((unsigned int*)sh)[i] = 0u;
    __syncthreads();
    const float4* o = obj4 + (size_t)img * N_ANCH4;
    int base = blockIdx.x * 2048 + t;
    float4 v[8]; bool m[8];
    #pragma unroll
    for (int u = 0; u < 8; u++) {
        int i = base + u * 256;
        m[u] = (i < N_ANCH4);
        v[u] = m[u] ? o[i] : make_float4(0.f, 0.f, 0.f, 0.f);
    }
    int p = (t >> 5) & 1;
    #pragma unroll
    for (int u = 0; u < 8; u++) if (m[u]) {
        atomicAdd(&sh[p][okey_of(v[u].x) >> 20], 1u);
        atomicAdd(&sh[p][okey_of(v[u].y) >> 20], 1u);
        atomicAdd(&sh[p][okey_of(v[u].z) >> 20], 1u);
        atomicAdd(&sh[p][okey_of(v[u].w) >> 20], 1u);
    }
    __syncthreads();
    for (int i = t; i < NBINS; i += 256) {
        unsigned int s = sh[0][i] + sh[1][i];
        if (s) atomicAdd(&g_hist[img * NBINS + i], s);
    }
}

// ---------------- threshold scan: 1 block/img, block suffix-scan, self-zeroing ----------------
__global__ void scan_kernel() {
    int img = blockIdx.x, t = threadIdx.x;   // 1024 threads
    __shared__ unsigned int wsums[32];
    int lane = t & 31, wid = t >> 5;
    int bi = t * 4;   // r index; bin = NBINS-1-r (descending bins)
    unsigned int c0 = g_hist[img * NBINS + (NBINS - 1 - (bi + 0))];
    unsigned int c1 = g_hist[img * NBINS + (NBINS - 1 - (bi + 1))];
    unsigned int c2 = g_hist[img * NBINS + (NBINS - 1 - (bi + 2))];
    unsigned int c3 = g_hist[img * NBINS + (NBINS - 1 - (bi + 3))];
    unsigned int s0 = c0, s1 = s0 + c1, s2 = s1 + c2, s3 = s2 + c3;
    unsigned int v = s3;
    #pragma unroll
    for (int off = 1; off < 32; off <<= 1) {
        unsigned int n = __shfl_up_sync(0xFFFFFFFFu, v, off);
        if (lane >= off) v += n;
    }
    if (lane == 31) wsums[wid] = v;
    __syncthreads();
    if (wid == 0) {
        unsigned int w = wsums[lane];
        #pragma unroll
        for (int off = 1; off < 32; off <<= 1) {
            unsigned int n = __shfl_up_sync(0xFFFFFFFFu, w, off);
            if (lane >= off) w += n;
        }
        wsums[lane] = w;
    }
    __syncthreads();
    unsigned int base = (wid > 0 ? wsums[wid - 1] : 0u) + (v - s3);
    if (base < K_PRE && base + s3 >= K_PRE) {
        int u = (base + s0 >= K_PRE) ? 0 : (base + s1 >= K_PRE) ? 1 : (base + s2 >= K_PRE) ? 2 : 3;
        g_state[img * 4 + 0] = (unsigned int)(NBINS - 1 - (bi + u)) << 20;
    }
    // zero own slots for next replay
    g_hist[img * NBINS + (NBINS - 1 - (bi + 0))] = 0u;
    g_hist[img * NBINS + (NBINS - 1 - (bi + 1))] = 0u;
    g_hist[img * NBINS + (NBINS - 1 - (bi + 2))] = 0u;
    g_hist[img * NBINS + (NBINS - 1 - (bi + 3))] = 0u;
}

// ---------------- compact candidates (key >= threshold), MLP=8 ----------------
__global__ void compact_kernel(const float4* __restrict__ obj4) {
    int img = blockIdx.y, t = threadIdx.x;
    unsigned int T = g_state[img * 4 + 0];
    const float4* o = obj4 + (size_t)img * N_ANCH4;
    int base = blockIdx.x * 2048 + t;
    float4 v[8]; bool m[8];
    #pragma unroll
    for (int u = 0; u < 8; u++) {
        int i = base + u * 256;
        m[u] = (i < N_ANCH4);
        v[u] = m[u] ? o[i] : make_float4(0.f, 0.f, 0.f, 0.f);
    }
    #pragma unroll
    for (int u = 0; u < 8; u++) if (m[u]) {
        int i = base + u * 256;
        #pragma unroll
        for (int c = 0; c < 4; c++) {
            float f = (c == 0) ? v[u].x : (c == 1) ? v[u].y : (c == 2) ? v[u].z : v[u].w;
            unsigned int k = okey_of(f);
            if (k >= T) {
                unsigned int pos = atomicAdd(&g_state[img * 4 + 2], 1u);
                if (pos < CAND_CAP)
                    g_cand[img * CAND_CAP + pos] =
                        ((ull)k << 32) | (unsigned int)(~(unsigned int)(4 * i + c));
            }
        }
    }
}

// ---------------- register/shfl bitonic sort of 4096 (desc) + fused decode ----------------
__device__ __forceinline__ void cas_reg(ull& a, ull& b, bool desc) {
    // desc: ensure a >= b ; asc: ensure a <= b
    if ((a < b) == desc) { ull tmp = a; a = b; b = tmp; }
}

__global__ void sortdec_kernel(const float* __restrict__ anchors,
                               const float* __restrict__ deltas) {
    int img = blockIdx.x, t = threadIdx.x;   // 1024 threads
    __shared__ ull sh[CAND_CAP];             // 32 KB
    int w = t >> 5, lane = t & 31;
    unsigned int cnt = g_state[img * 4 + 2];
    if (cnt > CAND_CAP) cnt = CAND_CAP;
    // element index: i = (w<<7) | (e<<5) | lane ; V=4 per thread
    ull v[4];
    #pragma unroll
    for (int e = 0; e < 4; e++) {
        int i = (w << 7) | (e << 5) | lane;
        v[e] = (i < (int)cnt) ? g_cand[img * CAND_CAP + i] : 0ull;
    }
    for (int k = 2; k <= CAND_CAP; k <<= 1) {
        if (k >= 256) {
            // cross-warp phases (j>=128) in smem
            #pragma unroll
            for (int e = 0; e < 4; e++) sh[(w << 7) | (e << 5) | lane] = v[e];
            __syncthreads();
            for (int j = k >> 1; j >= 128; j >>= 1) {
                for (int p = t; p < CAND_CAP / 2; p += 1024) {
                    int i = ((p & ~(j - 1)) << 1) | (p & (j - 1));
                    int ixj = i | j;
                    bool desc = ((i & k) == 0);
                    ull A = sh[i], B = sh[ixj];
                    if ((A < B) == desc) { sh[i] = B; sh[ixj] = A; }
                }
                __syncthreads();
            }
            #pragma unroll
            for (int e = 0; e < 4; e++) v[e] = sh[(w << 7) | (e << 5) | lane];
            // no sync needed: each thread re-reads exactly the slots it will overwrite next
        }
        if (k >= 128) {   // j = 64 : pairs (v0,v2),(v1,v3); direction set by w bits only
            bool d = (((w << 7) & k) == 0);
            cas_reg(v[0], v[2], d);
            cas_reg(v[1], v[3], d);
        }
        if (k >= 64) {    // j = 32 : pairs (v0,v1),(v2,v3)
            bool d01 = ((((w << 7) | (0 << 5)) & k) == 0);
            bool d23 = ((((w << 7) | (2 << 5)) & k) == 0);
            cas_reg(v[0], v[1], d01);
            cas_reg(v[2], v[3], d23);
        }
        int jmax = (k >> 1) < 16 ? (k >> 1) : 16;
        for (int j = jmax; j >= 1; j >>= 1) {
            #pragma unroll
            for (int e = 0; e < 4; e++) {
                int i = (w << 7) | (e << 5) | lane;
                bool desc = ((i & k) == 0);
                bool iLow = ((lane & j) == 0);
                ull p = __shfl_xor_sync(0xFFFFFFFFu, v[e], j);
                ull mx = (v[e] > p) ? v[e] : p;
                ull mn = (v[e] > p) ? p : v[e];
                v[e] = (iLow == desc) ? mx : mn;
            }
        }
    }
    #pragma unroll
    for (int e = 0; e < 4; e++) sh[(w << 7) | (e << 5) | lane] = v[e];
    __syncthreads();
    // fused decode of top-2000 (sorted descending in sh)
    for (int r = t; r < K_PRE; r += 1024) {
        ull e = sh[r];
        int idx = (int)(~(unsigned int)(e & 0xFFFFFFFFull));
        unsigned int kk = (unsigned int)(e >> 32);
        float score = __uint_as_float((kk & 0x80000000u) ? (kk ^ 0x80000000u) : ~kk);
        const float4 A = ((const float4*)anchors)[idx];
        const float4 D = ((const float4*)deltas)[(size_t)img * N_ANCH + idx];
        float w_  = __fadd_rn(__fsub_rn(A.z, A.x), 1.0f);
        float h_  = __fadd_rn(__fsub_rn(A.w, A.y), 1.0f);
        float cx = __fadd_rn(A.x, __fmul_rn(0.5f, w_));
        float cy = __fadd_rn(A.y, __fmul_rn(0.5f, h_));
        float dw = fminf(D.z, XFORM_CLIP);
        float dh = fminf(D.w, XFORM_CLIP);
        float pcx = __fadd_rn(__fmul_rn(D.x, w_), cx);
        float pcy = __fadd_rn(__fmul_rn(D.y, h_), cy);
        float pw  = __fmul_rn(__nv_expf(dw), w_);
        float ph  = __fmul_rn(__nv_expf(dh), h_);
        float hx = __fmul_rn(0.5f, pw), hy = __fmul_rn(0.5f, ph);
        float x1 = __fsub_rn(pcx, hx);
        float y1 = __fsub_rn(pcy, hy);
        float x2 = __fsub_rn(__fadd_rn(pcx, hx), 1.0f);
        float y2 = __fsub_rn(__fadd_rn(pcy, hy), 1.0f);
        x1 = fminf(fmaxf(x1, 0.0f), XMAX);
        x2 = fminf(fmaxf(x2, 0.0f), XMAX);
        y1 = fminf(fmaxf(y1, 0.0f), YMAX);
        y2 = fminf(fmaxf(y2, 0.0f), YMAX);
        float ww = __fadd_rn(__fsub_rn(x2, x1), 1.0f);
        float hh = __fadd_rn(__fsub_rn(y2, y1), 1.0f);
        g_props4[img * K_PRE + r] = make_float4(x1, y1, x2, y2);
        g_area[img * K_PRE + r] = __fmul_rn(ww, hh);
        g_valid[img * K_PRE + r] = (ww >= 0.0f && hh >= 0.0f) ? 1 : 0;
        g_scores[img * K_PRE + r] = score;
    }
    if (t == 0) g_state[img * 4 + 2] = 0u;   // reset for next replay
}

// ---------------- 64x64 IoU bitmask (triangular grid, div-free fast path) ----------------
__device__ __forceinline__ bool iou_sup(float4 a, float ai, float4 b, float aj) {
    float lx = fmaxf(a.x, b.x), ly = fmaxf(a.y, b.y);
    float rx = fminf(a.z, b.z), ry = fminf(a.w, b.w);
    float iw = fmaxf(__fadd_rn(__fsub_rn(rx, lx), 1.0f), 0.0f);
    float ih = fmaxf(__fadd_rn(__fsub_rn(ry, ly), 1.0f), 0.0f);
    float inter = __fmul_rn(iw, ih);
    float den = __fsub_rn(__fadd_rn(ai, aj), inter);
    float t = __fmaf_rn(-NMS_THRESH, den, inter);
    if (fabsf(t) <= __fmul_rn(1.2e-7f, den))
        return __fdiv_rn(inter, den) > NMS_THRESH;   // exact, rare
    return t > 0.0f;
}

__global__ void mask_kernel() {
    int img = blockIdx.y;
    int u = blockIdx.x;                 // 0..527 upper-tri tiles
    int rb = 0, rem = u;
    while (rem >= 32 - rb) { rem -= 32 - rb; rb++; }
    int cb = rb + rem;
    __shared__ float4 cbox[64];
    __shared__ float  car[64];
    int t = threadIdx.x;   // 64 threads
    int j0 = cb * 64, j = j0 + t;
    if (j < K_PRE) {
        cbox[t] = g_props4[img * K_PRE + j];
        car[t]  = g_area[img * K_PRE + j];
    }
    __syncthreads();
    int row = rb * 64 + t;
    if (row >= K_PRE) return;
    float4 rbox = g_props4[img * K_PRE + row];
    float ai = g_area[img * K_PRE + row];
    ull m = 0ull;
    int lim = K_PRE - j0; if (lim > 64) lim = 64;
    if (cb > rb) {
        #pragma unroll 4
        for (int jj = 0; jj < lim; jj++)
            if (iou_sup(rbox, ai, cbox[jj], car[jj])) m |= (1ull << jj);
    } else {
        for (int jj = t + 1; jj < lim; jj++)
            if (iou_sup(rbox, ai, cbox[jj], car[jj])) m |= (1ull << jj);
    }
    g_mask[((size_t)img * 2048 + row) * 32 + cb] = m;
}

// ---------------- greedy NMS (register-windowed chain) + fused partition/pack ----------------
__global__ void greedy_kernel(float* __restrict__ out) {
    int img = blockIdx.x, t = threadIdx.x;   // 256 threads
    __shared__ ull buf[2][2048];
    __shared__ ull skw[32];
    __shared__ int done;
    __shared__ int wsum[8];
    __shared__ int stot;
    const ull* M = &g_mask[(size_t)img * 2048 * 32];
    for (int i = t; i < 2048; i += 256) buf[0][i] = M[i];
    if (t < 32) skw[t] = 0ull;
    if (t == 0) done = 0;
    __syncthreads();
    int wid = t >> 5, lane = t & 31;
    ull removed = 0ull;
    if (wid == 0) {
        // fold invalid rows (and rows >= K_PRE) into removed: lane l owns rows l*64..l*64+63
        const ull* v8 = (const ull*)(g_valid + img * K_PRE);
        #pragma unroll
        for (int w = 0; w < 8; w++) {
            int wi = lane * 8 + w;
            ull x = (wi < K_PRE / 8) ? v8[wi] : 0ull;
            #pragma unroll
            for (int b = 0; b < 8; b++)
                if (!((x >> (8 * b)) & 0xFFull)) removed |= 1ull << (w * 8 + b);
        }
    }
    int nk = 0;
    for (int c = 0; c < 32; c++) {
        int cbuf = c & 1, nbuf = cbuf ^ 1;
        if (wid > 0 && (c + 1) < 32) {
            const ull* src = &M[(size_t)(c + 1) * 2048];
            for (int i = t - 32; i < 2048; i += 224) buf[nbuf][i] = src[i];
        }
        if (wid == 0) {
            ull cur = __shfl_sync(0xFFFFFFFFu, removed, c);
            ull kept = 0ull;
            int lim = K_PRE - c * 64; if (lim > 64) lim = 64;
            for (int qb = 0; qb < lim; qb += 8) {
                ull dw[8];
                #pragma unroll
                for (int r = 0; r < 8; r++)
                    dw[r] = buf[cbuf][(qb + r) * 32 + c];   // broadcast loads, pipelined
                #pragma unroll
                for (int r = 0; r < 8; r++) {
                    int q = qb + r;
                    if (q < lim && nk < K_POST && !((cur >> q) & 1ull)) {
                        kept |= 1ull << q;
                        cur |= dw[r];
                        nk++;
                    }
                }
            }
            if (lane == 0) skw[c] = kept;
            // batched removed accumulation (independent LDS, MLP-pipelined)
            ull kb = kept;
            while (kb) {
                int q = __ffsll((long long)kb) - 1;
                kb &= kb - 1;
                removed |= buf[cbuf][q * 32 + lane];
            }
            if (nk >= K_POST && lane == 0) done = 1;
        }
        __syncthreads();
        if (done) break;
    }
    // ---- fused stable-partition + pack (256 threads x 8 rows) ----
    ull chunkw = skw[t >> 3];
    unsigned int bits8 = (unsigned int)((chunkw >> ((t & 7) * 8)) & 0xFFull);
    int s = __popc(bits8);
    int v = s;
    #pragma unroll
    for (int off = 1; off < 32; off <<= 1) {
        int n = __shfl_up_sync(0xFFFFFFFFu, v, off);
        if (lane >= off) v += n;
    }
    if (lane == 31) wsum[wid] = v;
    __syncthreads();
    if (wid == 0 && lane < 8) {
        int w = wsum[lane];
        #pragma unroll
        for (int off = 1; off < 8; off <<= 1) {
            int n = __shfl_up_sync(0xFFu, w, off);
            if ((int)lane >= off) w += n;
        }
        wsum[lane] = w;
        if (lane == 7) stot = w;
    }
    __syncthreads();
    int base8 = (wid > 0 ? wsum[wid - 1] : 0) + (v - s);   // kept before row t*8
    int total = stot;
    #pragma unroll
    for (int qq = 0; qq < 8; qq++) {
        int rr = t * 8 + qq;
        if (rr >= K_PRE) break;
        int flag = (int)((bits8 >> qq) & 1u);
        int kb = base8 + __popc(bits8 & ((1u << qq) - 1u));
        int p = flag ? kb : total + (rr - kb);
        if (p < K_POST) {
            float4 P = g_props4[img * K_PRE + rr];
            float* o = &out[((size_t)img * K_POST + p) * 5];
            o[0] = P.x; o[1] = P.y; o[2] = P.z; o[3] = P.w;
            o[4] = flag ? g_scores[img * K_PRE + rr] : NEG_BIG;
        }
    }
}

// ---------------- launch ----------------
extern "C" void kernel_launch(void* const* d_in, const int* in_sizes, int n_in,
                              void* d_out, int out_size) {
    const float *anchors = nullptr, *obj = nullptr, *deltas = nullptr;
    for (int i = 0; i < n_in; i++) {
        if (in_sizes[i] == N_ANCH * 4)              anchors = (const float*)d_in[i];
        else if (in_sizes[i] == N_IMG * N_ANCH)     obj     = (const float*)d_in[i];
        else if (in_sizes[i] == N_IMG * N_ANCH * 4) deltas  = (const float*)d_in[i];
    }
    float* out = (float*)d_out;

    hist_kernel<<<dim3(31, N_IMG), 256>>>((const float4*)obj);
    scan_kernel<<<N_IMG, 1024>>>();
    compact_kernel<<<dim3(31, N_IMG), 256>>>((const float4*)obj);
    sortdec_kernel<<<N_IMG, 1024>>>(anchors, deltas);
    mask_kernel<<<dim3(528, N_IMG), 64>>>();
    greedy_kernel<<<N_IMG, 256>>>(out);
    (void)out_size;
}

// round 5
// speedup vs baseline: 1.2308x; 1.2308x over previous
#include <cuda_runtime.h>
#include <cstdint>

// libdevice precise expf (what XLA lowers jnp.exp(f32) to), immune to fast-math.
extern "C" __device__ float __nv_expf(float);

typedef unsigned long long ull;

// ---------------- problem constants ----------------
#define N_IMG 8
#define N_ANCH 250000
#define N_ANCH4 62500
#define K_PRE 2000
#define K_POST 1000
#define CAND_CAP 4096
#define NMS_THRESH 0.7f
#define XFORM_CLIP 4.135166556742356f
#define XMAX 1332.0f
#define YMAX 799.0f
#define NEG_BIG -1e9f
#define NBINS 4096

// ---------------- device scratch ----------------
__device__ unsigned int g_hist[N_IMG * NBINS];   // zero-init at load; self-zeroed by scan
__device__ unsigned int g_state[N_IMG * 4];      // [0]=threshold key, [2]=cand_cnt (reset by sortdec)
__device__ ull    g_cand[N_IMG * CAND_CAP];
__device__ float4 g_props4[N_IMG * K_PRE];
__device__ float  g_area[N_IMG * K_PRE];
__device__ float  g_scores[N_IMG * K_PRE];
__device__ unsigned char g_valid[N_IMG * K_PRE];
__device__ ull    g_mask[N_IMG * 2048 * 32];

__device__ __forceinline__ unsigned int okey_of(float f) {
    unsigned int b = __float_as_uint(f);
    return b ^ ((b & 0x80000000u) ? 0xFFFFFFFFu : 0x80000000u);
}

// ---------------- histogram (12-bit bins), MLP=8 tiled loads ----------------
__global__ void hist_kernel(const float4* __restrict__ obj4) {
    int img = blockIdx.y, t = threadIdx.x;
    __shared__ unsigned int sh[2][NBINS];
    for (int i = t; i < 2 * NBINS; i += 256) ((unsigned int*)sh)[i] = 0u;
    __syncthreads();
    const float4* o = obj4 + (size_t)img * N_ANCH4;
    int base = blockIdx.x * 2048 + t;
    float4 v[8]; bool m[8];
    #pragma unroll
    for (int u = 0; u < 8; u++) {
        int i = base + u * 256;
        m[u] = (i < N_ANCH4);
        v[u] = m[u] ? o[i] : make_float4(0.f, 0.f, 0.f, 0.f);
    }
    int p = (t >> 5) & 1;
    #pragma unroll
    for (int u = 0; u < 8; u++) if (m[u]) {
        atomicAdd(&sh[p][okey_of(v[u].x) >> 20], 1u);
        atomicAdd(&sh[p][okey_of(v[u].y) >> 20], 1u);
        atomicAdd(&sh[p][okey_of(v[u].z) >> 20], 1u);
        atomicAdd(&sh[p][okey_of(v[u].w) >> 20], 1u);
    }
    __syncthreads();
    for (int i = t; i < NBINS; i += 256) {
        unsigned int s = sh[0][i] + sh[1][i];
        if (s) atomicAdd(&g_hist[img * NBINS + i], s);
    }
}

// ---------------- threshold scan: 1 block/img, block suffix-scan, self-zeroing ----------------
__global__ void scan_kernel() {
    int img = blockIdx.x, t = threadIdx.x;   // 1024 threads
    __shared__ unsigned int wsums[32];
    int lane = t & 31, wid = t >> 5;
    int bi = t * 4;   // r index; bin = NBINS-1-r (descending bins)
    unsigned int c0 = g_hist[img * NBINS + (NBINS - 1 - (bi + 0))];
    unsigned int c1 = g_hist[img * NBINS + (NBINS - 1 - (bi + 1))];
    unsigned int c2 = g_hist[img * NBINS + (NBINS - 1 - (bi + 2))];
    unsigned int c3 = g_hist[img * NBINS + (NBINS - 1 - (bi + 3))];
    unsigned int s0 = c0, s1 = s0 + c1, s2 = s1 + c2, s3 = s2 + c3;
    unsigned int v = s3;
    #pragma unroll
    for (int off = 1; off < 32; off <<= 1) {
        unsigned int n = __shfl_up_sync(0xFFFFFFFFu, v, off);
        if (lane >= off) v += n;
    }
    if (lane == 31) wsums[wid] = v;
    __syncthreads();
    if (wid == 0) {
        unsigned int w = wsums[lane];
        #pragma unroll
        for (int off = 1; off < 32; off <<= 1) {
            unsigned int n = __shfl_up_sync(0xFFFFFFFFu, w, off);
            if (lane >= off) w += n;
        }
        wsums[lane] = w;
    }
    __syncthreads();
    unsigned int base = (wid > 0 ? wsums[wid - 1] : 0u) + (v - s3);
    if (base < K_PRE && base + s3 >= K_PRE) {
        int u = (base + s0 >= K_PRE) ? 0 : (base + s1 >= K_PRE) ? 1 : (base + s2 >= K_PRE) ? 2 : 3;
        g_state[img * 4 + 0] = (unsigned int)(NBINS - 1 - (bi + u)) << 20;
    }
    g_hist[img * NBINS + (NBINS - 1 - (bi + 0))] = 0u;
    g_hist[img * NBINS + (NBINS - 1 - (bi + 1))] = 0u;
    g_hist[img * NBINS + (NBINS - 1 - (bi + 2))] = 0u;
    g_hist[img * NBINS + (NBINS - 1 - (bi + 3))] = 0u;
}

// ---------------- compact candidates (key >= threshold), MLP=8 ----------------
__global__ void compact_kernel(const float4* __restrict__ obj4) {
    int img = blockIdx.y, t = threadIdx.x;
    unsigned int T = g_state[img * 4 + 0];
    const float4* o = obj4 + (size_t)img * N_ANCH4;
    int base = blockIdx.x * 2048 + t;
    float4 v[8]; bool m[8];
    #pragma unroll
    for (int u = 0; u < 8; u++) {
        int i = base + u * 256;
        m[u] = (i < N_ANCH4);
        v[u] = m[u] ? o[i] : make_float4(0.f, 0.f, 0.f, 0.f);
    }
    #pragma unroll
    for (int u = 0; u < 8; u++) if (m[u]) {
        int i = base + u * 256;
        #pragma unroll
        for (int c = 0; c < 4; c++) {
            float f = (c == 0) ? v[u].x : (c == 1) ? v[u].y : (c == 2) ? v[u].z : v[u].w;
            unsigned int k = okey_of(f);
            if (k >= T) {
                unsigned int pos = atomicAdd(&g_state[img * 4 + 2], 1u);
                if (pos < CAND_CAP)
                    g_cand[img * CAND_CAP + pos] =
                        ((ull)k << 32) | (unsigned int)(~(unsigned int)(4 * i + c));
            }
        }
    }
}

// ---------------- sort: refine to <=2048, then V=2 register/shfl bitonic ----------------
__device__ __forceinline__ void cas_reg(ull& a, ull& b, bool desc) {
    if ((a < b) == desc) { ull tmp = a; a = b; b = tmp; }
}

__global__ void sortdec_kernel(const float* __restrict__ anchors,
                               const float* __restrict__ deltas) {
    int img = blockIdx.x, t = threadIdx.x;   // 1024 threads
    __shared__ ull sh[CAND_CAP];             // 32 KB
    __shared__ unsigned int hist2[2048];     // 8 KB
    __shared__ unsigned int sR, sC2;
    __shared__ int c2cnt;
    int w = t >> 5, lane = t & 31;
    unsigned int cnt = g_state[img * 4 + 2];
    if (cnt > CAND_CAP) cnt = CAND_CAP;
    for (int i = t; i < CAND_CAP; i += 1024)
        sh[i] = (i < (int)cnt) ? g_cand[img * CAND_CAP + i] : 0ull;
    bool small = true;
    __syncthreads();
    if (cnt > 2048u) {
        // refine: 2048 finer bins of (key>>9) above quantized threshold
        for (int i = t; i < 2048; i += 1024) hist2[i] = 0u;
        __syncthreads();
        unsigned int Tq = g_state[img * 4 + 0] >> 9;
        for (int i = t; i < (int)cnt; i += 1024) {
            unsigned int k = (unsigned int)(sh[i] >> 32);
            unsigned int d = (k >> 9) - Tq; if (d > 2047u) d = 2047u;
            atomicAdd(&hist2[d], 1u);
        }
        __syncthreads();
        if (t < 32) {
            unsigned int cum = 0;
            for (int b2 = 2047; b2 >= 31; b2 -= 32) {
                int bin = b2 - t;
                unsigned int c = hist2[bin], vv = c;
                #pragma unroll
                for (int off = 1; off < 32; off <<= 1) {
                    unsigned int n = __shfl_up_sync(0xFFFFFFFFu, vv, off);
                    if (t >= off) vv += n;
                }
                unsigned int tot = __shfl_sync(0xFFFFFFFFu, vv, 31);
                unsigned int ball = __ballot_sync(0xFFFFFFFFu, cum + vv >= K_PRE);
                if (ball) {
                    int l = __ffs(ball) - 1;
                    if (t == l) { sR = (unsigned int)bin; sC2 = cum + vv; }
                    break;
                }
                cum += tot;
            }
            if (t == 0) c2cnt = 0;
        }
        __syncthreads();
        unsigned int R = sR, C2 = sC2;
        if (C2 <= 2048u) {
            ull mine[4]; bool q[4];
            #pragma unroll
            for (int u = 0; u < 4; u++) {
                int i = t + u * 1024;
                mine[u] = sh[i];
                unsigned int k = (unsigned int)(mine[u] >> 32);
                unsigned int d = (k >> 9) - Tq; if (d > 2047u) d = 2047u;
                q[u] = (i < (int)cnt) && (d >= R);
            }
            __syncthreads();
            #pragma unroll
            for (int u = 0; u < 4; u++) if (q[u]) {
                int pos = atomicAdd(&c2cnt, 1);
                sh[pos] = mine[u];
            }
            __syncthreads();
            for (int i = t; i < 2048; i += 1024) if (i >= c2cnt) sh[i] = 0ull;
            __syncthreads();
        } else {
            small = false;   // ultra-rare fallback: sort all 4096 in smem
        }
    }
    if (small) {
        // V=2 register/shfl bitonic over 2048 ; i = (w<<6)|(e<<5)|lane
        ull v[2];
        #pragma unroll
        for (int e = 0; e < 2; e++) v[e] = sh[(w << 6) | (e << 5) | lane];
        for (int k = 2; k <= 2048; k <<= 1) {
            if (k >= 128) {
                #pragma unroll
                for (int e = 0; e < 2; e++) sh[(w << 6) | (e << 5) | lane] = v[e];
                __syncthreads();
                for (int j = k >> 1; j >= 64; j >>= 1) {
                    int p = t;   // exactly 1024 pairs
                    int i = ((p & ~(j - 1)) << 1) | (p & (j - 1));
                    int ixj = i | j;
                    bool desc = ((i & k) == 0);
                    ull A = sh[i], B = sh[ixj];
                    if ((A < B) == desc) { sh[i] = B; sh[ixj] = A; }
                    __syncthreads();
                }
                #pragma unroll
                for (int e = 0; e < 2; e++) v[e] = sh[(w << 6) | (e << 5) | lane];
            }
            if (k >= 64) {   // j = 32 : pair (v0, v1)
                bool d = (((w << 6) & k) == 0);
                cas_reg(v[0], v[1], d);
            }
            int jmax = (k >> 1) < 16 ? (k >> 1) : 16;
            for (int j = jmax; j >= 1; j >>= 1) {
                #pragma unroll
                for (int e = 0; e < 2; e++) {
                    int i = (w << 6) | (e << 5) | lane;
                    bool desc = ((i & k) == 0);
                    bool iLow = ((lane & j) == 0);
                    ull p = __shfl_xor_sync(0xFFFFFFFFu, v[e], j);
                    ull mx = (v[e] > p) ? v[e] : p;
                    ull mn = (v[e] > p) ? p : v[e];
                    v[e] = (iLow == desc) ? mx : mn;
                }
            }
        }
        #pragma unroll
        for (int e = 0; e < 2; e++) sh[(w << 6) | (e << 5) | lane] = v[e];
        __syncthreads();
    } else {
        // plain smem bitonic over 4096 (correct, nearly never taken)
        for (int k = 2; k <= CAND_CAP; k <<= 1) {
            for (int j = k >> 1; j > 0; j >>= 1) {
                for (int i = t; i < CAND_CAP; i += 1024) {
                    int ixj = i ^ j;
                    if (ixj > i) {
                        bool desc = ((i & k) == 0);
                        ull A = sh[i], B = sh[ixj];
                        if (desc ? (A < B) : (A > B)) { sh[i] = B; sh[ixj] = A; }
                    }
                }
                __syncthreads();
            }
        }
    }
    // fused decode of top-2000 (sorted descending in sh)
    for (int r = t; r < K_PRE; r += 1024) {
        ull e = sh[r];
        int idx = (int)(~(unsigned int)(e & 0xFFFFFFFFull));
        unsigned int kk = (unsigned int)(e >> 32);
        float score = __uint_as_float((kk & 0x80000000u) ? (kk ^ 0x80000000u) : ~kk);
        const float4 A = ((const float4*)anchors)[idx];
        const float4 D = ((const float4*)deltas)[(size_t)img * N_ANCH + idx];
        float w_  = __fadd_rn(__fsub_rn(A.z, A.x), 1.0f);
        float h_  = __fadd_rn(__fsub_rn(A.w, A.y), 1.0f);
        float cx = __fadd_rn(A.x, __fmul_rn(0.5f, w_));
        float cy = __fadd_rn(A.y, __fmul_rn(0.5f, h_));
        float dw = fminf(D.z, XFORM_CLIP);
        float dh = fminf(D.w, XFORM_CLIP);
        float pcx = __fadd_rn(__fmul_rn(D.x, w_), cx);
        float pcy = __fadd_rn(__fmul_rn(D.y, h_), cy);
        float pw  = __fmul_rn(__nv_expf(dw), w_);
        float ph  = __fmul_rn(__nv_expf(dh), h_);
        float hx = __fmul_rn(0.5f, pw), hy = __fmul_rn(0.5f, ph);
        float x1 = __fsub_rn(pcx, hx);
        float y1 = __fsub_rn(pcy, hy);
        float x2 = __fsub_rn(__fadd_rn(pcx, hx), 1.0f);
        float y2 = __fsub_rn(__fadd_rn(pcy, hy), 1.0f);
        x1 = fminf(fmaxf(x1, 0.0f), XMAX);
        x2 = fminf(fmaxf(x2, 0.0f), XMAX);
        y1 = fminf(fmaxf(y1, 0.0f), YMAX);
        y2 = fminf(fmaxf(y2, 0.0f), YMAX);
        float ww = __fadd_rn(__fsub_rn(x2, x1), 1.0f);
        float hh = __fadd_rn(__fsub_rn(y2, y1), 1.0f);
        g_props4[img * K_PRE + r] = make_float4(x1, y1, x2, y2);
        g_area[img * K_PRE + r] = __fmul_rn(ww, hh);
        g_valid[img * K_PRE + r] = (ww >= 0.0f && hh >= 0.0f) ? 1 : 0;
        g_scores[img * K_PRE + r] = score;
    }
    if (t == 0) g_state[img * 4 + 2] = 0u;   // reset for next replay
}

// ---------------- IoU test (div-free fast path, exact fallback) ----------------
__device__ __forceinline__ bool iou_sup(float4 a, float ai, float4 b, float aj) {
    float lx = fmaxf(a.x, b.x), ly = fmaxf(a.y, b.y);
    float rx = fminf(a.z, b.z), ry = fminf(a.w, b.w);
    float iw = fmaxf(__fadd_rn(__fsub_rn(rx, lx), 1.0f), 0.0f);
    float ih = fmaxf(__fadd_rn(__fsub_rn(ry, ly), 1.0f), 0.0f);
    float inter = __fmul_rn(iw, ih);
    float den = __fsub_rn(__fadd_rn(ai, aj), inter);
    float t = __fmaf_rn(-NMS_THRESH, den, inter);
    if (fabsf(t) <= __fmul_rn(1.2e-7f, den))
        return __fdiv_rn(inter, den) > NMS_THRESH;   // exact, rare
    return t > 0.0f;
}

// ---------------- 64x64 IoU tiles: warp-per-row, register columns, ballot ----------------
__global__ void mask_kernel() {
    int img = blockIdx.y;
    int u = blockIdx.x;                 // 0..527 upper-tri tiles
    int rb = 0, rem = u;
    while (rem >= 32 - rb) { rem -= 32 - rb; rb++; }
    int cb = rb + rem;
    int t = threadIdx.x;                // 256 threads, 8 warps
    int wid = t >> 5, lane = t & 31;
    __shared__ float4 rbox_s[64];
    __shared__ float  rar_s[64];
    int r0 = rb * 64, j0 = cb * 64;
    if (t < 64) {
        int r = r0 + t;
        if (r < K_PRE) { rbox_s[t] = g_props4[img * K_PRE + r]; rar_s[t] = g_area[img * K_PRE + r]; }
    }
    int jA = j0 + lane, jB = j0 + lane + 32;
    float4 bA = (jA < K_PRE) ? g_props4[img * K_PRE + jA] : make_float4(1e9f, 1e9f, -1e9f, -1e9f);
    float4 bB = (jB < K_PRE) ? g_props4[img * K_PRE + jB] : make_float4(1e9f, 1e9f, -1e9f, -1e9f);
    float aA = (jA < K_PRE) ? g_area[img * K_PRE + jA] : 0.f;
    float aB = (jB < K_PRE) ? g_area[img * K_PRE + jB] : 0.f;
    __syncthreads();
    bool diag = (cb == rb);
    for (int rr = wid; rr < 64; rr += 8) {
        int row = r0 + rr;
        if (row >= K_PRE) continue;    // warp-uniform
        float4 a = rbox_s[rr];
        float ai = rar_s[rr];
        bool sA = iou_sup(a, ai, bA, aA);
        bool sB = iou_sup(a, ai, bB, aB);
        if (diag) { sA = sA && (jA > row); sB = sB && (jB > row); }
        unsigned int lo = __ballot_sync(0xFFFFFFFFu, sA);
        unsigned int hi = __ballot_sync(0xFFFFFFFFu, sB);
        if (lane == 0)
            g_mask[((size_t)img * 2048 + row) * 32 + cb] = (ull)lo | ((ull)hi << 32);
    }
}

// ---------------- greedy NMS (R2 structure + register windows) + fused pack ----------------
__global__ void greedy_kernel(float* __restrict__ out) {
    int img = blockIdx.x, t = threadIdx.x;   // 256 threads
    __shared__ ull buf[2][2048];
    __shared__ unsigned char sk[2048];
    __shared__ int done;
    __shared__ int wsum[8];
    __shared__ int stot;
    const ull* M = &g_mask[(size_t)img * 2048 * 32];
    for (int i = t; i < 2048; i += 256) { sk[i] = 0; buf[0][i] = M[i]; }
    if (t == 0) done = 0;
    __syncthreads();
    int wid = t >> 5, lane = t & 31;
    ull removed = 0ull;
    if (wid == 0) {
        const ull* v8 = (const ull*)(g_valid + img * K_PRE);
        #pragma unroll
        for (int w = 0; w < 8; w++) {
            int wi = lane * 8 + w;
            ull x = (wi < K_PRE / 8) ? v8[wi] : 0ull;
            #pragma unroll
            for (int b = 0; b < 8; b++)
                if (!((x >> (8 * b)) & 0xFFull)) removed |= 1ull << (w * 8 + b);
        }
    }
    int nk = 0;
    for (int c = 0; c < 32; c++) {
        int cbuf = c & 1, nbuf = cbuf ^ 1;
        if (wid > 0 && (c + 1) < 32) {
            const ull* src = &M[(size_t)(c + 1) * 2048];
            for (int i = t - 32; i < 2048; i += 224) buf[nbuf][i] = src[i];
        }
        if (wid == 0) {
            ull cur = __shfl_sync(0xFFFFFFFFu, removed, c);
            int base = c * 64;
            int lim = K_PRE - base; if (lim > 64) lim = 64;
            for (int qb = 0; qb < lim; qb += 8) {
                ull dw[8];
                #pragma unroll
                for (int r = 0; r < 8; r++)
                    dw[r] = buf[cbuf][(qb + r) * 32 + c];   // broadcast, off critical path
                #pragma unroll
                for (int r = 0; r < 8; r++) {
                    int q = qb + r;
                    if (q < lim && nk < K_POST && !((cur >> q) & 1ull)) {
                        if (lane == 0) sk[base + q] = 1;
                        removed |= buf[cbuf][q * 32 + lane];
                        cur |= dw[r];
                        nk++;
                    }
                }
            }
            if (nk >= K_POST && lane == 0) done = 1;
        }
        __syncthreads();
        if (done) break;
    }
    // ---- fused stable-partition + pack (256 threads x 8 rows) ----
    ull f8 = ((const ull*)sk)[t];
    int s = __popcll(f8);
    int v = s;
    #pragma unroll
    for (int off = 1; off < 32; off <<= 1) {
        int n = __shfl_up_sync(0xFFFFFFFFu, v, off);
        if (lane >= off) v += n;
    }
    if (lane == 31) wsum[wid] = v;
    __syncthreads();
    if (wid == 0 && lane < 8) {
        int w = wsum[lane];
        #pragma unroll
        for (int off = 1; off < 8; off <<= 1) {
            int n = __shfl_up_sync(0xFFu, w, off);
            if ((int)lane >= off) w += n;
        }
        wsum[lane] = w;
        if (lane == 7) stot = w;
    }
    __syncthreads();
    int base8 = (wid > 0 ? wsum[wid - 1] : 0) + (v - s);
    int total = stot;
    #pragma unroll
    for (int qq = 0; qq < 8; qq++) {
        int rr = t * 8 + qq;
        if (rr >= K_PRE) break;
        int flag = (int)((f8 >> (8 * qq)) & 1ull);
        ull low = (qq == 0) ? 0ull : (f8 & ((1ull << (8 * qq)) - 1ull));
        int kb = base8 + __popcll(low);
        int p = flag ? kb : total + (rr - kb);
        if (p < K_POST) {
            float4 P = g_props4[img * K_PRE + rr];
            float* o = &out[((size_t)img * K_POST + p) * 5];
            o[0] = P.x; o[1] = P.y; o[2] = P.z; o[3] = P.w;
            o[4] = flag ? g_scores[img * K_PRE + rr] : NEG_BIG;
        }
    }
}

// ---------------- launch ----------------
extern "C" void kernel_launch(void* const* d_in, const int* in_sizes, int n_in,
                              void* d_out, int out_size) {
    const float *anchors = nullptr, *obj = nullptr, *deltas = nullptr;
    for (int i = 0; i < n_in; i++) {
        if (in_sizes[i] == N_ANCH * 4)              anchors = (const float*)d_in[i];
        else if (in_sizes[i] == N_IMG * N_ANCH)     obj     = (const float*)d_in[i];
        else if (in_sizes[i] == N_IMG * N_ANCH * 4) deltas  = (const float*)d_in[i];
    }
    float* out = (float*)d_out;

    hist_kernel<<<dim3(31, N_IMG), 256>>>((const float4*)obj);
    scan_kernel<<<N_IMG, 1024>>>();
    compact_kernel<<<dim3(31, N_IMG), 256>>>((const float4*)obj);
    sortdec_kernel<<<N_IMG, 1024>>>(anchors, deltas);
    mask_kernel<<<dim3(528, N_IMG), 256>>>();
    greedy_kernel<<<N_IMG, 256>>>(out);
    (void)out_size;
}